// round 1
// baseline (speedup 1.0000x reference)
#include <cuda_runtime.h>
#include <math.h>

// Problem constants
#define S_LEN  2048
#define BATCH  2
#define EMB    768
#define NHEAD  12
#define HD     64
#define NH     (BATCH*NHEAD)        // 24 flattened heads
#define M_ROWS (S_LEN*BATCH)        // 4096
#define OUT0   (S_LEN*BATCH*EMB)    // 3145728 floats (output tensor)
// attn_weights elements: NH * S * S = 100663296

// ---------------- device scratch (static, allocation-free) ----------------
__device__ float g_Qh[NH * S_LEN * HD];   // [head, s, d]
__device__ float g_Kh[NH * S_LEN * HD];
__device__ float g_Vh[NH * S_LEN * HD];
__device__ float g_ctx[M_ROWS * EMB];     // attn_output in [S,B,E] layout
__device__ float g_m[NH * S_LEN];         // per-row softmax max
__device__ float g_l[NH * S_LEN];         // per-row softmax sum

// ============================================================================
// Kernel A: QKV projection GEMM.  out = X @ W^T + b, written split-head.
// X: [M_ROWS, EMB] row-major (rows m = s*B + b).  W: [EMB, EMB] row-major.
// Tile: 64x64, BK=16, 256 threads, 4x4 per thread.
// Output col n = h*64 + d; tile col block == head (BN == HD == 64).
// sel: 0 -> g_Qh, 1 -> g_Kh, 2 -> g_Vh
// ============================================================================
__global__ __launch_bounds__(256) void gemm_qkv_kernel(
    const float* __restrict__ X, const float* __restrict__ W,
    const float* __restrict__ bias, int sel)
{
    __shared__ float As[16 * 64];   // transposed: As[k*64 + m]
    __shared__ float Bs[16 * 65];   // transposed: Bs[k*65 + n] (pad 65)

    const int tid = threadIdx.x;
    const int tx = tid & 15, ty = tid >> 4;
    const int m0 = blockIdx.x * 64;
    const int n0 = blockIdx.y * 64;
    const int h  = blockIdx.y;           // head index within E

    const int lrow = tid >> 2;           // 0..63
    const int lk   = (tid & 3) * 4;      // 0,4,8,12

    float acc[4][4] = {};

    for (int k0 = 0; k0 < EMB; k0 += 16) {
        float4 av = *(const float4*)&X[(size_t)(m0 + lrow) * EMB + k0 + lk];
        float4 bv = *(const float4*)&W[(size_t)(n0 + lrow) * EMB + k0 + lk];
        __syncthreads();
        As[(lk + 0) * 64 + lrow] = av.x;
        As[(lk + 1) * 64 + lrow] = av.y;
        As[(lk + 2) * 64 + lrow] = av.z;
        As[(lk + 3) * 64 + lrow] = av.w;
        Bs[(lk + 0) * 65 + lrow] = bv.x;
        Bs[(lk + 1) * 65 + lrow] = bv.y;
        Bs[(lk + 2) * 65 + lrow] = bv.z;
        Bs[(lk + 3) * 65 + lrow] = bv.w;
        __syncthreads();
        #pragma unroll
        for (int k = 0; k < 16; k++) {
            float4 a4 = *(const float4*)&As[k * 64 + ty * 4];
            float b0 = Bs[k * 65 + tx * 4 + 0];
            float b1 = Bs[k * 65 + tx * 4 + 1];
            float b2 = Bs[k * 65 + tx * 4 + 2];
            float b3 = Bs[k * 65 + tx * 4 + 3];
            acc[0][0] += a4.x * b0; acc[0][1] += a4.x * b1; acc[0][2] += a4.x * b2; acc[0][3] += a4.x * b3;
            acc[1][0] += a4.y * b0; acc[1][1] += a4.y * b1; acc[1][2] += a4.y * b2; acc[1][3] += a4.y * b3;
            acc[2][0] += a4.z * b0; acc[2][1] += a4.z * b1; acc[2][2] += a4.z * b2; acc[2][3] += a4.z * b3;
            acc[3][0] += a4.w * b0; acc[3][1] += a4.w * b1; acc[3][2] += a4.w * b2; acc[3][3] += a4.w * b3;
        }
    }

    float* outH = (sel == 0) ? g_Qh : (sel == 1) ? g_Kh : g_Vh;
    float bb0 = bias[n0 + tx * 4 + 0];
    float bb1 = bias[n0 + tx * 4 + 1];
    float bb2 = bias[n0 + tx * 4 + 2];
    float bb3 = bias[n0 + tx * 4 + 3];
    #pragma unroll
    for (int i = 0; i < 4; i++) {
        int m = m0 + ty * 4 + i;
        int s = m >> 1;            // m = s*BATCH + b, BATCH=2
        int b = m & 1;
        int head = b * NHEAD + h;
        float4 st = make_float4(acc[i][0] + bb0, acc[i][1] + bb1,
                                acc[i][2] + bb2, acc[i][3] + bb3);
        *(float4*)&outH[((size_t)head * S_LEN + s) * HD + tx * 4] = st;
    }
}

// ============================================================================
// Kernel B: flash attention per (head, 64-query tile).
// Streams K tiles, computes score tile (written raw to weights region),
// online softmax, P@V accumulation; writes ctx + per-row (m, l).
// Dynamic smem: Qs[64*64] + KV[64*65] + Ps[64*64] = 12352 floats = 49408 B.
// ============================================================================
#define FLASH_SMEM_FLOATS (4096 + 4160 + 4096)
#define FLASH_SMEM_BYTES  (FLASH_SMEM_FLOATS * 4)

__global__ __launch_bounds__(256) void flash_kernel(float* __restrict__ wraw)
{
    extern __shared__ float sm[];
    float* Qs  = sm;               // [r*64 + e]  natural
    float* KVs = sm + 4096;        // K: [e*65 + c] transposed; V: [k*64 + d] natural
    float* Ps  = sm + 4096 + 4160; // [r*64 + k]  natural

    const int tid = threadIdx.x;
    const int tx = tid & 15, ty = tid >> 4;
    const int n  = blockIdx.y;          // flattened head 0..23
    const int q0 = blockIdx.x * 64;

    const float* Qbase = g_Qh + ((size_t)n * S_LEN + q0) * HD;
    const float* Kbase = g_Kh + (size_t)n * S_LEN * HD;
    const float* Vbase = g_Vh + (size_t)n * S_LEN * HD;

    // load Q tile (natural layout)
    #pragma unroll
    for (int rr = 0; rr < 4; rr++) {
        int r = rr * 16 + ty;
        float4 v = *(const float4*)&Qbase[r * HD + tx * 4];
        *(float4*)&Qs[r * 64 + tx * 4] = v;
    }

    float m_i[4], l_i[4], o[4][4];
    #pragma unroll
    for (int i = 0; i < 4; i++) {
        m_i[i] = -INFINITY; l_i[i] = 0.f;
        o[i][0] = o[i][1] = o[i][2] = o[i][3] = 0.f;
    }

    for (int kt = 0; kt < S_LEN / 64; kt++) {
        __syncthreads();   // prev PV done reading KVs; Q stores visible (iter 0)
        // load K tile transposed: KVs[e*65 + c]
        #pragma unroll
        for (int rr = 0; rr < 4; rr++) {
            int r = rr * 16 + ty;
            float4 v = *(const float4*)&Kbase[(size_t)(kt * 64 + r) * HD + tx * 4];
            KVs[(tx * 4 + 0) * 65 + r] = v.x;
            KVs[(tx * 4 + 1) * 65 + r] = v.y;
            KVs[(tx * 4 + 2) * 65 + r] = v.z;
            KVs[(tx * 4 + 3) * 65 + r] = v.w;
        }
        __syncthreads();

        // S tile = Q K^T / 8
        float s[4][4] = {};
        #pragma unroll 8
        for (int e = 0; e < 64; e++) {
            float a0 = Qs[(ty * 4 + 0) * 64 + e];
            float a1 = Qs[(ty * 4 + 1) * 64 + e];
            float a2 = Qs[(ty * 4 + 2) * 64 + e];
            float a3 = Qs[(ty * 4 + 3) * 64 + e];
            float b0 = KVs[e * 65 + tx * 4 + 0];
            float b1 = KVs[e * 65 + tx * 4 + 1];
            float b2 = KVs[e * 65 + tx * 4 + 2];
            float b3 = KVs[e * 65 + tx * 4 + 3];
            s[0][0] += a0 * b0; s[0][1] += a0 * b1; s[0][2] += a0 * b2; s[0][3] += a0 * b3;
            s[1][0] += a1 * b0; s[1][1] += a1 * b1; s[1][2] += a1 * b2; s[1][3] += a1 * b3;
            s[2][0] += a2 * b0; s[2][1] += a2 * b1; s[2][2] += a2 * b2; s[2][3] += a2 * b3;
            s[3][0] += a3 * b0; s[3][1] += a3 * b1; s[3][2] += a3 * b2; s[3][3] += a3 * b3;
        }
        #pragma unroll
        for (int i = 0; i < 4; i++) {
            s[i][0] *= 0.125f; s[i][1] *= 0.125f; s[i][2] *= 0.125f; s[i][3] *= 0.125f;
        }

        // raw (pre-softmax) scores -> weights region (normalized later)
        if (wraw) {
            #pragma unroll
            for (int i = 0; i < 4; i++) {
                *(float4*)&wraw[((size_t)n * S_LEN + q0 + ty * 4 + i) * S_LEN
                                + kt * 64 + tx * 4] =
                    make_float4(s[i][0], s[i][1], s[i][2], s[i][3]);
            }
        }

        // online softmax update (row reductions across tx via half-warp shuffles)
        #pragma unroll
        for (int i = 0; i < 4; i++) {
            float tm = fmaxf(fmaxf(s[i][0], s[i][1]), fmaxf(s[i][2], s[i][3]));
            #pragma unroll
            for (int off = 8; off > 0; off >>= 1)
                tm = fmaxf(tm, __shfl_xor_sync(0xffffffffu, tm, off));
            float nm = fmaxf(m_i[i], tm);
            float p0 = __expf(s[i][0] - nm);
            float p1 = __expf(s[i][1] - nm);
            float p2 = __expf(s[i][2] - nm);
            float p3 = __expf(s[i][3] - nm);
            float ts = p0 + p1 + p2 + p3;
            #pragma unroll
            for (int off = 8; off > 0; off >>= 1)
                ts += __shfl_xor_sync(0xffffffffu, ts, off);
            float sc = __expf(m_i[i] - nm);
            l_i[i] = l_i[i] * sc + ts;
            m_i[i] = nm;
            o[i][0] *= sc; o[i][1] *= sc; o[i][2] *= sc; o[i][3] *= sc;
            *(float4*)&Ps[(ty * 4 + i) * 64 + tx * 4] = make_float4(p0, p1, p2, p3);
        }

        __syncthreads();   // Ps written, K reads done -> reuse KVs for V
        #pragma unroll
        for (int rr = 0; rr < 4; rr++) {
            int r = rr * 16 + ty;
            float4 v = *(const float4*)&Vbase[(size_t)(kt * 64 + r) * HD + tx * 4];
            *(float4*)&KVs[r * 64 + tx * 4] = v;
        }
        __syncthreads();

        // O += P @ V
        #pragma unroll 8
        for (int k = 0; k < 64; k++) {
            float a0 = Ps[(ty * 4 + 0) * 64 + k];
            float a1 = Ps[(ty * 4 + 1) * 64 + k];
            float a2 = Ps[(ty * 4 + 2) * 64 + k];
            float a3 = Ps[(ty * 4 + 3) * 64 + k];
            float b0 = KVs[k * 64 + tx * 4 + 0];
            float b1 = KVs[k * 64 + tx * 4 + 1];
            float b2 = KVs[k * 64 + tx * 4 + 2];
            float b3 = KVs[k * 64 + tx * 4 + 3];
            o[0][0] += a0 * b0; o[0][1] += a0 * b1; o[0][2] += a0 * b2; o[0][3] += a0 * b3;
            o[1][0] += a1 * b0; o[1][1] += a1 * b1; o[1][2] += a1 * b2; o[1][3] += a1 * b3;
            o[2][0] += a2 * b0; o[2][1] += a2 * b1; o[2][2] += a2 * b2; o[2][3] += a2 * b3;
            o[3][0] += a3 * b0; o[3][1] += a3 * b1; o[3][2] += a3 * b2; o[3][3] += a3 * b3;
        }
    }

    // epilogue: normalize, scatter ctx back to [S,B,E], save (m,l)
    const int bI = n / NHEAD;
    const int hI = n % NHEAD;
    #pragma unroll
    for (int i = 0; i < 4; i++) {
        float inv = 1.f / l_i[i];
        int sr = q0 + ty * 4 + i;
        float4 st = make_float4(o[i][0] * inv, o[i][1] * inv,
                                o[i][2] * inv, o[i][3] * inv);
        *(float4*)&g_ctx[((size_t)sr * BATCH + bI) * EMB + hI * HD + tx * 4] = st;
        if (tx == 0) {
            g_m[n * S_LEN + sr] = m_i[i];
            g_l[n * S_LEN + sr] = l_i[i];
        }
    }
}

// ============================================================================
// Kernel C: normalize raw scores in place: w = exp(s - m[row]) / l[row]
// ============================================================================
__global__ __launch_bounds__(256) void softmax_norm_kernel(float* __restrict__ w)
{
    size_t i4 = (size_t)blockIdx.x * blockDim.x + threadIdx.x;  // float4 index
    size_t row = i4 / (S_LEN / 4);                              // NH*S rows
    float m = g_m[row];
    float inv = 1.f / g_l[row];
    float4* wv = (float4*)w + i4;
    float4 v = *wv;
    v.x = __expf(v.x - m) * inv;
    v.y = __expf(v.y - m) * inv;
    v.z = __expf(v.z - m) * inv;
    v.w = __expf(v.w - m) * inv;
    *wv = v;
}

// ============================================================================
// Kernel D: output projection. out = ctx @ W_O^T + b_O, plain [M,E] output.
// ============================================================================
__global__ __launch_bounds__(256) void gemm_out_kernel(
    const float* __restrict__ W, const float* __restrict__ bias,
    float* __restrict__ out)
{
    __shared__ float As[16 * 64];
    __shared__ float Bs[16 * 65];

    const int tid = threadIdx.x;
    const int tx = tid & 15, ty = tid >> 4;
    const int m0 = blockIdx.x * 64;
    const int n0 = blockIdx.y * 64;
    const int lrow = tid >> 2;
    const int lk   = (tid & 3) * 4;

    float acc[4][4] = {};

    for (int k0 = 0; k0 < EMB; k0 += 16) {
        float4 av = *(const float4*)&g_ctx[(size_t)(m0 + lrow) * EMB + k0 + lk];
        float4 bv = *(const float4*)&W[(size_t)(n0 + lrow) * EMB + k0 + lk];
        __syncthreads();
        As[(lk + 0) * 64 + lrow] = av.x;
        As[(lk + 1) * 64 + lrow] = av.y;
        As[(lk + 2) * 64 + lrow] = av.z;
        As[(lk + 3) * 64 + lrow] = av.w;
        Bs[(lk + 0) * 65 + lrow] = bv.x;
        Bs[(lk + 1) * 65 + lrow] = bv.y;
        Bs[(lk + 2) * 65 + lrow] = bv.z;
        Bs[(lk + 3) * 65 + lrow] = bv.w;
        __syncthreads();
        #pragma unroll
        for (int k = 0; k < 16; k++) {
            float4 a4 = *(const float4*)&As[k * 64 + ty * 4];
            float b0 = Bs[k * 65 + tx * 4 + 0];
            float b1 = Bs[k * 65 + tx * 4 + 1];
            float b2 = Bs[k * 65 + tx * 4 + 2];
            float b3 = Bs[k * 65 + tx * 4 + 3];
            acc[0][0] += a4.x * b0; acc[0][1] += a4.x * b1; acc[0][2] += a4.x * b2; acc[0][3] += a4.x * b3;
            acc[1][0] += a4.y * b0; acc[1][1] += a4.y * b1; acc[1][2] += a4.y * b2; acc[1][3] += a4.y * b3;
            acc[2][0] += a4.z * b0; acc[2][1] += a4.z * b1; acc[2][2] += a4.z * b2; acc[2][3] += a4.z * b3;
            acc[3][0] += a4.w * b0; acc[3][1] += a4.w * b1; acc[3][2] += a4.w * b2; acc[3][3] += a4.w * b3;
        }
    }

    float bb0 = bias[n0 + tx * 4 + 0];
    float bb1 = bias[n0 + tx * 4 + 1];
    float bb2 = bias[n0 + tx * 4 + 2];
    float bb3 = bias[n0 + tx * 4 + 3];
    #pragma unroll
    for (int i = 0; i < 4; i++) {
        float4 st = make_float4(acc[i][0] + bb0, acc[i][1] + bb1,
                                acc[i][2] + bb2, acc[i][3] + bb3);
        *(float4*)&out[(size_t)(m0 + ty * 4 + i) * EMB + n0 + tx * 4] = st;
    }
}

// ============================================================================
extern "C" void kernel_launch(void* const* d_in, const int* in_sizes, int n_in,
                              void* d_out, int out_size)
{
    const float* q   = (const float*)d_in[0];
    const float* k   = (const float*)d_in[1];
    const float* v   = (const float*)d_in[2];
    const float* W_Q = (const float*)d_in[3];
    const float* W_K = (const float*)d_in[4];
    const float* W_V = (const float*)d_in[5];
    const float* b_Q = (const float*)d_in[6];
    const float* b_K = (const float*)d_in[7];
    const float* b_V = (const float*)d_in[8];
    const float* W_O = (const float*)d_in[9];
    const float* b_O = (const float*)d_in[10];
    float* out = (float*)d_out;

    const long long NW_LL = (long long)NH * S_LEN * S_LEN;  // 100663296
    const long long total = (long long)OUT0 + NW_LL;
    float* wraw = ((long long)out_size >= total) ? (out + OUT0) : nullptr;

    // opt-in to >48KB dynamic smem for the flash kernel (capture-time host call)
    cudaFuncSetAttribute(flash_kernel,
                         cudaFuncAttributeMaxDynamicSharedMemorySize,
                         FLASH_SMEM_BYTES);

    dim3 gA(M_ROWS / 64, EMB / 64);  // 64 x 12
    gemm_qkv_kernel<<<gA, 256>>>(q, W_Q, b_Q, 0);
    gemm_qkv_kernel<<<gA, 256>>>(k, W_K, b_K, 1);
    gemm_qkv_kernel<<<gA, 256>>>(v, W_V, b_V, 2);

    dim3 gB(S_LEN / 64, NH);         // 32 x 24
    flash_kernel<<<gB, 256, FLASH_SMEM_BYTES>>>(wraw);

    if (wraw) {
        long long n4 = NW_LL / 4;                 // 25165824 float4s
        int blocks = (int)(n4 / 256);             // exact: 98304
        softmax_norm_kernel<<<blocks, 256>>>(wraw);
    }

    gemm_out_kernel<<<gA, 256>>>(W_O, b_O, out);
}

// round 7
// speedup vs baseline: 2.7454x; 2.7454x over previous
#include <cuda_runtime.h>
#include <math.h>

// Problem constants
#define S_LEN  2048
#define BATCH  2
#define EMB    768
#define NHEAD  12
#define HD     64
#define NH     (BATCH*NHEAD)        // 24 flattened heads
#define M_ROWS (S_LEN*BATCH)        // 4096
#define OUT0   (S_LEN*BATCH*EMB)    // 3145728 floats (output tensor)

// ---------------- device scratch (static, allocation-free) ----------------
__device__ float g_Qh[NH * S_LEN * HD];   // [head, s, d]
__device__ float g_Kh[NH * S_LEN * HD];
__device__ float g_Vh[NH * S_LEN * HD];
__device__ float g_ctx[M_ROWS * EMB];     // attn_output in [S,B,E] layout
__device__ float g_m[NH * S_LEN];         // per-row softmax max
__device__ float g_l[NH * S_LEN];         // per-row softmax sum

// ============================================================================
// portable (compute_103-safe) helpers: mma.sync tf32, cp.async, cvt.rna
// tf32 m16n8k8 fragment layouts (PTX ISA):
//  A (16x8):  a0=(g, t)  a1=(g+8, t)  a2=(g, t+4)  a3=(g+8, t+4)   [g=lane>>2, t=lane&3]
//  B (8x8):   b0=(k=t, n=g)  b1=(k=t+4, n=g)
//  C (16x8):  c0=(g, 2t) c1=(g, 2t+1) c2=(g+8, 2t) c3=(g+8, 2t+1)
// ============================================================================
__device__ __forceinline__ unsigned sm_addr(const void* p) {
    unsigned a;
    asm("{ .reg .u64 t; cvta.to.shared.u64 t, %1; cvt.u32.u64 %0, t; }" : "=r"(a) : "l"(p));
    return a;
}
__device__ __forceinline__ unsigned f2tf(float x) {
    unsigned r;
    asm("cvt.rna.tf32.f32 %0, %1;" : "=r"(r) : "f"(x));
    return r;
}
__device__ __forceinline__ void mma_tf(float c[4], unsigned a0, unsigned a1,
                                       unsigned a2, unsigned a3,
                                       unsigned b0, unsigned b1) {
    asm volatile(
        "mma.sync.aligned.m16n8k8.row.col.f32.tf32.tf32.f32 "
        "{%0,%1,%2,%3}, {%4,%5,%6,%7}, {%8,%9}, {%0,%1,%2,%3};"
        : "+f"(c[0]), "+f"(c[1]), "+f"(c[2]), "+f"(c[3])
        : "r"(a0), "r"(a1), "r"(a2), "r"(a3), "r"(b0), "r"(b1));
}
__device__ __forceinline__ void cpa16(unsigned saddr, const void* gptr) {
    asm volatile("cp.async.cg.shared.global [%0], [%1], 16;" :: "r"(saddr), "l"(gptr));
}
#define CP_COMMIT()  asm volatile("cp.async.commit_group;")
#define CP_WAIT0()   asm volatile("cp.async.wait_group 0;")
#define CP_WAIT1()   asm volatile("cp.async.wait_group 1;")

// ============================================================================
// Projection GEMM core: C[128x128] = A[128x768] @ B[128x768]^T (both K-major).
// 8 warps (2x4): warp tile 64m x 32n; K-chunks of 32, cp.async double-buffered.
// PLD=36: bank(row*36 + t) = 4g+t over a warp -> conflict-free scalar LDS.
// ============================================================================
#define PLD 36
#define PROJ_SMEM (4 * 128 * PLD * 4)   // 73728 B

__device__ __forceinline__ void proj_core(const float* __restrict__ Ag,
                                          const float* __restrict__ Bg,
                                          float (&acc)[4][4][4], float* sh)
{
    float* Ab[2] = { sh,                 sh + 128 * PLD };
    float* Bb[2] = { sh + 2 * 128 * PLD, sh + 3 * 128 * PLD };
    const int tid = threadIdx.x;
    const int lane = tid & 31, wid = tid >> 5;
    const int g = lane >> 2, t = lane & 3;
    const int wy = wid >> 2, wx = wid & 3;

    auto stage = [&](int c, int bs) {
        #pragma unroll
        for (int i = 0; i < 4; i++) {
            int idx = tid + 256 * i;               // 0..1023
            int row = idx >> 3, c4 = (idx & 7) * 4;
            cpa16(sm_addr(&Ab[bs][row * PLD + c4]), Ag + (size_t)row * EMB + c * 32 + c4);
            cpa16(sm_addr(&Bb[bs][row * PLD + c4]), Bg + (size_t)row * EMB + c * 32 + c4);
        }
        CP_COMMIT();
    };

    stage(0, 0);
    for (int c = 0; c < 24; c++) {
        __syncthreads();                 // prev compute finished before overwrite
        if (c + 1 < 24) { stage(c + 1, (c + 1) & 1); CP_WAIT1(); }
        else           { CP_WAIT0(); }
        __syncthreads();                 // chunk c visible to all

        const float* Af = Ab[c & 1];
        const float* Bf = Bb[c & 1];
        #pragma unroll
        for (int ks = 0; ks < 4; ks++) {
            const int k0s = 8 * ks;
            unsigned a[4][4];
            #pragma unroll
            for (int mt = 0; mt < 4; mt++) {
                int ra = (64 * wy + 16 * mt + g) * PLD + k0s;
                a[mt][0] = f2tf(Af[ra + t]);
                a[mt][1] = f2tf(Af[ra + 8 * PLD + t]);
                a[mt][2] = f2tf(Af[ra + t + 4]);
                a[mt][3] = f2tf(Af[ra + 8 * PLD + t + 4]);
            }
            #pragma unroll
            for (int nt = 0; nt < 4; nt++) {
                int rb = (32 * wx + 8 * nt + g) * PLD + k0s;
                unsigned b0 = f2tf(Bf[rb + t]);
                unsigned b1 = f2tf(Bf[rb + t + 4]);
                #pragma unroll
                for (int mt = 0; mt < 4; mt++)
                    mma_tf(acc[mt][nt], a[mt][0], a[mt][1], a[mt][2], a[mt][3], b0, b1);
            }
        }
    }
}

// ============================================================================
// Kernel A: fused QKV projection.  grid (32, 6, 3); split-head output.
// ============================================================================
__global__ __launch_bounds__(256, 2) void qkv_gemm(
    const float* __restrict__ q, const float* __restrict__ k, const float* __restrict__ v,
    const float* __restrict__ WQ, const float* __restrict__ WK, const float* __restrict__ WV,
    const float* __restrict__ bQ, const float* __restrict__ bK, const float* __restrict__ bV)
{
    extern __shared__ float sh[];
    const int m0 = blockIdx.x * 128, n0 = blockIdx.y * 128, sel = blockIdx.z;
    const float* X    = (sel == 0) ? q  : (sel == 1) ? k  : v;
    const float* W    = (sel == 0) ? WQ : (sel == 1) ? WK : WV;
    const float* bias = (sel == 0) ? bQ : (sel == 1) ? bK : bV;
    float* dst        = (sel == 0) ? g_Qh : (sel == 1) ? g_Kh : g_Vh;

    float acc[4][4][4] = {};
    proj_core(X + (size_t)m0 * EMB, W + (size_t)n0 * EMB, acc, sh);

    const int tid = threadIdx.x, lane = tid & 31, wid = tid >> 5;
    const int g = lane >> 2, t = lane & 3;
    const int wy = wid >> 2, wx = wid & 3;
    #pragma unroll
    for (int mt = 0; mt < 4; mt++) {
        #pragma unroll
        for (int nt = 0; nt < 4; nt++) {
            int n = n0 + 32 * wx + 8 * nt + 2 * t;
            int h = n >> 6, d0 = n & 63;
            float bb0 = bias[n], bb1 = bias[n + 1];
            int row = m0 + 64 * wy + 16 * mt + g;
            {
                int s = row >> 1, bI = row & 1;
                float2 st = make_float2(acc[mt][nt][0] + bb0, acc[mt][nt][1] + bb1);
                *(float2*)&dst[((size_t)(bI * NHEAD + h) * S_LEN + s) * HD + d0] = st;
            }
            {
                int r2 = row + 8;
                int s = r2 >> 1, bI = r2 & 1;
                float2 st = make_float2(acc[mt][nt][2] + bb0, acc[mt][nt][3] + bb1);
                *(float2*)&dst[((size_t)(bI * NHEAD + h) * S_LEN + s) * HD + d0] = st;
            }
        }
    }
}

// ============================================================================
// Kernel D: output projection.  grid (32, 6); out = ctx @ W_O^T + b_O.
// ============================================================================
__global__ __launch_bounds__(256, 2) void out_gemm(
    const float* __restrict__ W, const float* __restrict__ bias, float* __restrict__ out)
{
    extern __shared__ float sh[];
    const int m0 = blockIdx.x * 128, n0 = blockIdx.y * 128;

    float acc[4][4][4] = {};
    proj_core(g_ctx + (size_t)m0 * EMB, W + (size_t)n0 * EMB, acc, sh);

    const int tid = threadIdx.x, lane = tid & 31, wid = tid >> 5;
    const int g = lane >> 2, t = lane & 3;
    const int wy = wid >> 2, wx = wid & 3;
    #pragma unroll
    for (int mt = 0; mt < 4; mt++) {
        #pragma unroll
        for (int nt = 0; nt < 4; nt++) {
            int n = n0 + 32 * wx + 8 * nt + 2 * t;
            float bb0 = bias[n], bb1 = bias[n + 1];
            int row = m0 + 64 * wy + 16 * mt + g;
            *(float2*)&out[(size_t)row * EMB + n] =
                make_float2(acc[mt][nt][0] + bb0, acc[mt][nt][1] + bb1);
            *(float2*)&out[(size_t)(row + 8) * EMB + n] =
                make_float2(acc[mt][nt][2] + bb0, acc[mt][nt][3] + bb1);
        }
    }
}

// ============================================================================
// Kernel B: flash attention, tf32 mma.  grid (16, 24), 256 thr, 2 CTA/SM.
// Warp w owns q-rows [16w,16w+16); full 64-k per warp (quad-local softmax).
// P round-trips through a per-warp smem tile (C-layout store, A-layout load).
// Pads: Q/K/P = 68 (bank 4g+t, conflict-free), V = 72 (bank 8t+g, conflict-free).
// ============================================================================
#define QPAD 68
#define KPAD 68
#define VPAD 72
#define PPAD 68
#define FLASH_SMEM ((128*QPAD + 64*KPAD + 64*VPAD + 128*PPAD) * 4)   // 105472 B

__global__ __launch_bounds__(256, 2) void flash_tc(float* __restrict__ wraw)
{
    extern __shared__ float sh[];
    float* Qs = sh;                          // [128][QPAD] tf32 bits after preamble
    float* Ks = Qs + 128 * QPAD;             // [64][KPAD]  raw f32
    float* Vs = Ks + 64 * KPAD;              // [64][VPAD]  raw f32
    float* Ps = Vs + 64 * VPAD;              // [128][PPAD] per-warp P tiles (tf32 bits)

    const int tid = threadIdx.x, lane = tid & 31, wid = tid >> 5;
    const int g = lane >> 2, t = lane & 3;
    const int hn = blockIdx.y;               // flattened head
    const int q0 = blockIdx.x * 128;

    const float* Qb = g_Qh + ((size_t)hn * S_LEN + q0) * HD;
    const float* Kb = g_Kh + (size_t)hn * S_LEN * HD;
    const float* Vb = g_Vh + (size_t)hn * S_LEN * HD;

    // preamble: stage Q, K0, V0
    #pragma unroll
    for (int i = 0; i < 8; i++) {
        int idx = tid + 256 * i; int row = idx >> 4, c4 = (idx & 15) * 4;
        cpa16(sm_addr(&Qs[row * QPAD + c4]), Qb + (size_t)row * HD + c4);
    }
    #pragma unroll
    for (int i = 0; i < 4; i++) {
        int idx = tid + 256 * i; int row = idx >> 4, c4 = (idx & 15) * 4;
        cpa16(sm_addr(&Ks[row * KPAD + c4]), Kb + (size_t)row * HD + c4);
        cpa16(sm_addr(&Vs[row * VPAD + c4]), Vb + (size_t)row * HD + c4);
    }
    CP_COMMIT();
    CP_WAIT0();
    __syncthreads();
    // convert Q to tf32 bits in place (reused 32x)
    #pragma unroll
    for (int i = 0; i < 8; i++) {
        int idx = tid + 256 * i; int row = idx >> 4, c4 = (idx & 15) * 4;
        float4* p = (float4*)&Qs[row * QPAD + c4];
        float4 vv = *p;
        vv.x = __uint_as_float(f2tf(vv.x));
        vv.y = __uint_as_float(f2tf(vv.y));
        vv.z = __uint_as_float(f2tf(vv.z));
        vv.w = __uint_as_float(f2tf(vv.w));
        *p = vv;
    }

    float m0 = -INFINITY, m1 = -INFINITY, l0 = 0.f, l1 = 0.f;
    float oa[8][4] = {};
    const int qr = 16 * wid + g;             // warp-local base row (second = qr+8)
    float* Pw = Ps + wid * 16 * PPAD;        // per-warp P tile

    for (int kt = 0; kt < 32; kt++) {
        __syncthreads();                     // kt=0: Q conv visible; kt>0: tail pair
        if (kt) { CP_WAIT0(); __syncthreads(); }   // K(kt), V(kt) landed + visible

        // ---- S = Q @ K^T / 8 ----
        float sa[8][4] = {};
        #pragma unroll
        for (int k8 = 0; k8 < 8; k8++) {
            int ra = qr * QPAD + 8 * k8;
            unsigned a0 = __float_as_uint(Qs[ra + t]);
            unsigned a1 = __float_as_uint(Qs[ra + 8 * QPAD + t]);
            unsigned a2 = __float_as_uint(Qs[ra + t + 4]);
            unsigned a3 = __float_as_uint(Qs[ra + 8 * QPAD + t + 4]);
            #pragma unroll
            for (int nt = 0; nt < 8; nt++) {
                int rb = (8 * nt + g) * KPAD + 8 * k8;
                mma_tf(sa[nt], a0, a1, a2, a3,
                       f2tf(Ks[rb + t]), f2tf(Ks[rb + t + 4]));
            }
        }
        #pragma unroll
        for (int nt = 0; nt < 8; nt++) {
            sa[nt][0] *= 0.125f; sa[nt][1] *= 0.125f;
            sa[nt][2] *= 0.125f; sa[nt][3] *= 0.125f;
        }

        __syncthreads();                     // all warps done reading Ks
        if (kt < 31) {                       // prefetch K(kt+1) under softmax+PV
            #pragma unroll
            for (int i = 0; i < 4; i++) {
                int idx = tid + 256 * i; int row = idx >> 4, c4 = (idx & 15) * 4;
                cpa16(sm_addr(&Ks[row * KPAD + c4]),
                      Kb + (size_t)((kt + 1) * 64 + row) * HD + c4);
            }
            CP_COMMIT();
        }

        // ---- raw scores -> weights region (C layout: cols 2t,2t+1) ----
        if (wraw) {
            size_t rb0 = ((size_t)hn * S_LEN + (q0 + qr)) * S_LEN + (size_t)kt * 64 + 2 * t;
            #pragma unroll
            for (int nt = 0; nt < 8; nt++) {
                *(float2*)&wraw[rb0 + 8 * nt] = make_float2(sa[nt][0], sa[nt][1]);
                *(float2*)&wraw[rb0 + 8 * nt + 8 * (size_t)S_LEN] =
                    make_float2(sa[nt][2], sa[nt][3]);
            }
        }

        // ---- online softmax (row qr via c0/c1, row qr+8 via c2/c3) ----
        float lm0 = -INFINITY, lm1 = -INFINITY;
        #pragma unroll
        for (int nt = 0; nt < 8; nt++) {
            lm0 = fmaxf(lm0, fmaxf(sa[nt][0], sa[nt][1]));
            lm1 = fmaxf(lm1, fmaxf(sa[nt][2], sa[nt][3]));
        }
        lm0 = fmaxf(lm0, __shfl_xor_sync(0xffffffffu, lm0, 1));
        lm0 = fmaxf(lm0, __shfl_xor_sync(0xffffffffu, lm0, 2));
        lm1 = fmaxf(lm1, __shfl_xor_sync(0xffffffffu, lm1, 1));
        lm1 = fmaxf(lm1, __shfl_xor_sync(0xffffffffu, lm1, 2));
        float nm0 = fmaxf(m0, lm0), nm1 = fmaxf(m1, lm1);
        float ts0 = 0.f, ts1 = 0.f;
        #pragma unroll
        for (int nt = 0; nt < 8; nt++) {
            float p0 = __expf(sa[nt][0] - nm0);
            float p1 = __expf(sa[nt][1] - nm0);
            float p2 = __expf(sa[nt][2] - nm1);
            float p3 = __expf(sa[nt][3] - nm1);
            ts0 += p0 + p1; ts1 += p2 + p3;
            sa[nt][0] = __uint_as_float(f2tf(p0));   // tf32 bits, C layout
            sa[nt][1] = __uint_as_float(f2tf(p1));
            sa[nt][2] = __uint_as_float(f2tf(p2));
            sa[nt][3] = __uint_as_float(f2tf(p3));
        }
        ts0 += __shfl_xor_sync(0xffffffffu, ts0, 1);
        ts0 += __shfl_xor_sync(0xffffffffu, ts0, 2);
        ts1 += __shfl_xor_sync(0xffffffffu, ts1, 1);
        ts1 += __shfl_xor_sync(0xffffffffu, ts1, 2);
        float sc0 = __expf(m0 - nm0), sc1 = __expf(m1 - nm1);
        l0 = l0 * sc0 + ts0; l1 = l1 * sc1 + ts1;
        m0 = nm0; m1 = nm1;
        #pragma unroll
        for (int nt = 0; nt < 8; nt++) {
            oa[nt][0] *= sc0; oa[nt][1] *= sc0;
            oa[nt][2] *= sc1; oa[nt][3] *= sc1;
        }

        // ---- P: C-layout store to per-warp tile, A-layout reload ----
        #pragma unroll
        for (int nt = 0; nt < 8; nt++) {
            *(float2*)&Pw[g * PPAD + 8 * nt + 2 * t] =
                make_float2(sa[nt][0], sa[nt][1]);
            *(float2*)&Pw[(g + 8) * PPAD + 8 * nt + 2 * t] =
                make_float2(sa[nt][2], sa[nt][3]);
        }
        __syncwarp();

        // ---- O += P @ V ----
        #pragma unroll
        for (int k8 = 0; k8 < 8; k8++) {
            int pa = g * PPAD + 8 * k8;
            unsigned a0 = __float_as_uint(Pw[pa + t]);
            unsigned a1 = __float_as_uint(Pw[pa + 8 * PPAD + t]);
            unsigned a2 = __float_as_uint(Pw[pa + t + 4]);
            unsigned a3 = __float_as_uint(Pw[pa + 8 * PPAD + t + 4]);
            #pragma unroll
            for (int nt = 0; nt < 8; nt++) {
                int vb = (8 * k8 + t) * VPAD + 8 * nt + g;
                mma_tf(oa[nt], a0, a1, a2, a3,
                       f2tf(Vs[vb]), f2tf(Vs[vb + 4 * VPAD]));
            }
        }
        __syncthreads();                     // all warps done reading Vs
        if (kt < 31) {                       // prefetch V(kt+1)
            #pragma unroll
            for (int i = 0; i < 4; i++) {
                int idx = tid + 256 * i; int row = idx >> 4, c4 = (idx & 15) * 4;
                cpa16(sm_addr(&Vs[row * VPAD + c4]),
                      Vb + (size_t)((kt + 1) * 64 + row) * HD + c4);
            }
            CP_COMMIT();
        }
    }

    // epilogue: normalize, scatter to [S,B,E], save (m,l)
    float inv0 = 1.f / l0, inv1 = 1.f / l1;
    const int r0 = q0 + qr, r1 = r0 + 8;
    const int bI = hn / NHEAD, hI = hn % NHEAD;
    #pragma unroll
    for (int nt = 0; nt < 8; nt++) {
        int d0 = 8 * nt + 2 * t;
        *(float2*)&g_ctx[((size_t)r0 * BATCH + bI) * EMB + hI * HD + d0] =
            make_float2(oa[nt][0] * inv0, oa[nt][1] * inv0);
        *(float2*)&g_ctx[((size_t)r1 * BATCH + bI) * EMB + hI * HD + d0] =
            make_float2(oa[nt][2] * inv1, oa[nt][3] * inv1);
    }
    if (t == 0) {
        g_m[hn * S_LEN + r0] = m0; g_m[hn * S_LEN + r1] = m1;
        g_l[hn * S_LEN + r0] = l0; g_l[hn * S_LEN + r1] = l1;
    }
}

// ============================================================================
// Kernel C: normalize raw scores in place: w = exp(s - m[row]) / l[row]
// ============================================================================
__global__ __launch_bounds__(256) void softmax_norm_kernel(float* __restrict__ w)
{
    size_t i4 = (size_t)blockIdx.x * blockDim.x + threadIdx.x;
    size_t row = i4 / (S_LEN / 4);
    float m = g_m[row];
    float inv = 1.f / g_l[row];
    float4* wv = (float4*)w + i4;
    float4 v = *wv;
    v.x = __expf(v.x - m) * inv;
    v.y = __expf(v.y - m) * inv;
    v.z = __expf(v.z - m) * inv;
    v.w = __expf(v.w - m) * inv;
    *wv = v;
}

// ============================================================================
extern "C" void kernel_launch(void* const* d_in, const int* in_sizes, int n_in,
                              void* d_out, int out_size)
{
    const float* q   = (const float*)d_in[0];
    const float* k   = (const float*)d_in[1];
    const float* v   = (const float*)d_in[2];
    const float* W_Q = (const float*)d_in[3];
    const float* W_K = (const float*)d_in[4];
    const float* W_V = (const float*)d_in[5];
    const float* b_Q = (const float*)d_in[6];
    const float* b_K = (const float*)d_in[7];
    const float* b_V = (const float*)d_in[8];
    const float* W_O = (const float*)d_in[9];
    const float* b_O = (const float*)d_in[10];
    float* out = (float*)d_out;

    const long long NW_LL = (long long)NH * S_LEN * S_LEN;  // 100663296
    const long long total = (long long)OUT0 + NW_LL;
    float* wraw = ((long long)out_size >= total) ? (out + OUT0) : nullptr;

    cudaFuncSetAttribute(qkv_gemm,
                         cudaFuncAttributeMaxDynamicSharedMemorySize, PROJ_SMEM);
    cudaFuncSetAttribute(out_gemm,
                         cudaFuncAttributeMaxDynamicSharedMemorySize, PROJ_SMEM);
    cudaFuncSetAttribute(flash_tc,
                         cudaFuncAttributeMaxDynamicSharedMemorySize, FLASH_SMEM);

    dim3 gQKV(M_ROWS / 128, EMB / 128, 3);   // 32 x 6 x 3
    qkv_gemm<<<gQKV, 256, PROJ_SMEM>>>(q, k, v, W_Q, W_K, W_V, b_Q, b_K, b_V);

    dim3 gB(S_LEN / 128, NH);                // 16 x 24
    flash_tc<<<gB, 256, FLASH_SMEM>>>(wraw);

    if (wraw) {
        long long n4 = NW_LL / 4;
        int blocks = (int)(n4 / 256);        // 98304
        softmax_norm_kernel<<<blocks, 256>>>(wraw);
    }

    dim3 gO(M_ROWS / 128, EMB / 128);        // 32 x 6
    out_gemm<<<gO, 256, PROJ_SMEM>>>(W_O, b_O, out);
}